// round 4
// baseline (speedup 1.0000x reference)
#include <cuda_runtime.h>
#include <cuda_bf16.h>
#include <math.h>

// Problem constants
#define BATCH 4
#define SLEN  2048
#define EDIM  1024
#define NH    16
#define HDIM  64
#define QKVW  3072            // 3*E
#define HSTRIDE 192           // 3*HD per head inside qkv row
#define NTILE 16              // SLEN / 128

// ---------------------------------------------------------------------------
// Scratch (device globals: allocation is forbidden)
// ---------------------------------------------------------------------------
__device__ float g_qkv [(size_t)BATCH * SLEN * QKVW];        // [B*S, 3E]
__device__ float g_vals[(size_t)BATCH * SLEN * EDIM];        // [B*S, E]
__device__ float g_mrun[(size_t)BATCH * NH * SLEN * NTILE];  // running max per (row, ktile)
__device__ float g_lfin[(size_t)BATCH * NH * SLEN];          // final denom per row

// ---------------------------------------------------------------------------
// SIMT fp32 GEMM: C[M,N] = A[M,K] * B[K,N] + bias[N]
// BM=BN=128, BK=16, 256 threads, 8x8 microtile, register double-buffering.
// ---------------------------------------------------------------------------
#define ASTR 132   // padded stride for transposed A tile (2-way stores, aligned reads)

__global__ __launch_bounds__(256)
void sgemm_bias(const float* __restrict__ A, const float* __restrict__ B,
                const float* __restrict__ bias, float* __restrict__ C,
                int M, int N, int K) {
    __shared__ float As[2][16 * ASTR];
    __shared__ float Bs[2][16 * 128];

    const int tid = threadIdx.x;
    const int tx  = tid & 15;
    const int ty  = tid >> 4;
    const int row0 = blockIdx.y * 128;
    const int col0 = blockIdx.x * 128;

    // A tile: 128 rows x 16 cols -> 512 float4 / 256 thr = 2 per thread
    const int aRow  = tid >> 1;
    const int aCol0 = (tid & 1) << 3;
    // B tile: 16 rows x 128 cols -> 512 float4 / 256 thr = 2 per thread
    const int bRow  = tid >> 4;
    const int bCol0 = (tid & 15) << 2;

    float4 pa0, pa1, pb0, pb1;

    const float* Abase = A + (size_t)(row0 + aRow) * K;
    const float* Bbase = B + (size_t)bRow * N + col0;

    // prefetch tile 0
    pa0 = *(const float4*)(Abase + aCol0);
    pa1 = *(const float4*)(Abase + aCol0 + 4);
    pb0 = *(const float4*)(Bbase + bCol0);
    pb1 = *(const float4*)(Bbase + bCol0 + 64);

    float acc[8][8];
#pragma unroll
    for (int i = 0; i < 8; i++)
#pragma unroll
        for (int j = 0; j < 8; j++) acc[i][j] = 0.f;

    // store tile 0
    {
        float* as = As[0];
        as[(aCol0 + 0) * ASTR + aRow] = pa0.x;
        as[(aCol0 + 1) * ASTR + aRow] = pa0.y;
        as[(aCol0 + 2) * ASTR + aRow] = pa0.z;
        as[(aCol0 + 3) * ASTR + aRow] = pa0.w;
        as[(aCol0 + 4) * ASTR + aRow] = pa1.x;
        as[(aCol0 + 5) * ASTR + aRow] = pa1.y;
        as[(aCol0 + 6) * ASTR + aRow] = pa1.z;
        as[(aCol0 + 7) * ASTR + aRow] = pa1.w;
        *(float4*)&Bs[0][bRow * 128 + bCol0]      = pb0;
        *(float4*)&Bs[0][bRow * 128 + bCol0 + 64] = pb1;
    }
    __syncthreads();

    const int nt = K >> 4;
    for (int kt = 0; kt < nt; kt++) {
        if (kt + 1 < nt) {
            const int k0 = (kt + 1) << 4;
            pa0 = *(const float4*)(Abase + k0 + aCol0);
            pa1 = *(const float4*)(Abase + k0 + aCol0 + 4);
            pb0 = *(const float4*)(Bbase + (size_t)k0 * N + bCol0);
            pb1 = *(const float4*)(Bbase + (size_t)k0 * N + bCol0 + 64);
        }
        const int buf = kt & 1;
        const float* as = As[buf];
        const float* bs = Bs[buf];
#pragma unroll
        for (int kk = 0; kk < 16; kk++) {
            float ra[8], rb[8];
#pragma unroll
            for (int i = 0; i < 8; i++) ra[i] = as[kk * ASTR + ty * 8 + i];
#pragma unroll
            for (int j = 0; j < 8; j++) rb[j] = bs[kk * 128 + tx * 8 + j];
#pragma unroll
            for (int i = 0; i < 8; i++)
#pragma unroll
                for (int j = 0; j < 8; j++) acc[i][j] += ra[i] * rb[j];
        }
        if (kt + 1 < nt) {
            float* asn = As[buf ^ 1];
            asn[(aCol0 + 0) * ASTR + aRow] = pa0.x;
            asn[(aCol0 + 1) * ASTR + aRow] = pa0.y;
            asn[(aCol0 + 2) * ASTR + aRow] = pa0.z;
            asn[(aCol0 + 3) * ASTR + aRow] = pa0.w;
            asn[(aCol0 + 4) * ASTR + aRow] = pa1.x;
            asn[(aCol0 + 5) * ASTR + aRow] = pa1.y;
            asn[(aCol0 + 6) * ASTR + aRow] = pa1.z;
            asn[(aCol0 + 7) * ASTR + aRow] = pa1.w;
            *(float4*)&Bs[buf ^ 1][bRow * 128 + bCol0]      = pb0;
            *(float4*)&Bs[buf ^ 1][bRow * 128 + bCol0 + 64] = pb1;
            __syncthreads();
        }
    }

#pragma unroll
    for (int i = 0; i < 8; i++) {
        const int r = row0 + ty * 8 + i;
#pragma unroll
        for (int j = 0; j < 8; j += 4) {
            const int c = col0 + tx * 8 + j;
            float4 v;
            v.x = acc[i][j + 0] + bias[c + 0];
            v.y = acc[i][j + 1] + bias[c + 1];
            v.z = acc[i][j + 2] + bias[c + 2];
            v.w = acc[i][j + 3] + bias[c + 3];
            *(float4*)&C[(size_t)r * N + c] = v;
        }
    }
}

// ---------------------------------------------------------------------------
// Single-pass flash attention, 128x128 tiles, 8x8 microtile.
// Writes UNNORMALIZED exp(s - m_running) to attn_out; records m per tile and
// final l; fixup kernel normalizes afterwards. O computed exactly (flash).
// ---------------------------------------------------------------------------
#define TSTR 132   // padded stride for transposed Q/K tiles and Ps

// shared floats: Qs 64*132 + Ks 64*132 + Vs 128*64 + Ps 128*132
#define ATT_SM_FLOATS (64*TSTR + 64*TSTR + 128*64 + 128*TSTR)
#define ATT_SM_BYTES  (ATT_SM_FLOATS * 4)

__global__ __launch_bounds__(256)
void attn_kernel(const float* __restrict__ qkv,
                 float* __restrict__ attn_out,   // [B,H,S,S] (unnormalized this pass)
                 float* __restrict__ mrun,
                 float* __restrict__ lfin,
                 float* __restrict__ vals) {     // [B,S,E]
    extern __shared__ float sm[];
    float* Qs = sm;                       // [64][TSTR]  (d-major)
    float* Ks = Qs + 64 * TSTR;           // [64][TSTR]  (d-major)
    float* Vs = Ks + 64 * TSTR;           // [128][64]   (natural)
    float* Ps = Vs + 128 * 64;            // [128][TSTR]

    const int qt  = (NTILE - 1) - blockIdx.x;   // heavy tiles first
    const int bh  = blockIdx.y;
    const int b   = bh >> 4;
    const int h   = bh & 15;
    const int tid = threadIdx.x;
    const int tx  = tid & 15;
    const int ty  = tid >> 4;
    const int q0  = qt * 128;

    // ---- load Q transposed: Qs[d][m] ----
    {
        const float* qbase = qkv + ((size_t)b * SLEN + q0) * QKVW + h * HSTRIDE;
#pragma unroll
        for (int i = 0; i < 8; i++) {
            int lin = i * 256 + tid;
            int r   = lin >> 4;
            int c4  = (lin & 15) << 2;
            float4 v = *(const float4*)(qbase + (size_t)r * QKVW + c4);
            Qs[(c4 + 0) * TSTR + r] = v.x;
            Qs[(c4 + 1) * TSTR + r] = v.y;
            Qs[(c4 + 2) * TSTR + r] = v.z;
            Qs[(c4 + 3) * TSTR + r] = v.w;
        }
    }

    float m_st[8], l_st[8], o[8][4];
#pragma unroll
    for (int i = 0; i < 8; i++) {
        m_st[i] = -INFINITY;
        l_st[i] = 0.f;
#pragma unroll
        for (int j = 0; j < 4; j++) o[i][j] = 0.f;
    }
    __syncthreads();

    const float scale = 0.125f;   // 1/sqrt(64)
    float* const abh = attn_out + (size_t)bh * SLEN * SLEN;

    for (int kt = 0; kt <= qt; kt++) {
        const int k0 = kt * 128;
        // ---- load K (transposed) and V (natural) ----
        {
            const float* kbase = qkv + ((size_t)b * SLEN + k0) * QKVW + h * HSTRIDE + HDIM;
            const float* vbase = kbase + HDIM;
#pragma unroll
            for (int i = 0; i < 8; i++) {
                int lin = i * 256 + tid;
                int r   = lin >> 4;
                int c4  = (lin & 15) << 2;
                float4 kv = *(const float4*)(kbase + (size_t)r * QKVW + c4);
                float4 vv = *(const float4*)(vbase + (size_t)r * QKVW + c4);
                Ks[(c4 + 0) * TSTR + r] = kv.x;
                Ks[(c4 + 1) * TSTR + r] = kv.y;
                Ks[(c4 + 2) * TSTR + r] = kv.z;
                Ks[(c4 + 3) * TSTR + r] = kv.w;
                *(float4*)&Vs[r * 64 + c4] = vv;
            }
        }
        __syncthreads();

        // ---- S = Q K^T (8x8 per thread) ----
        float s[8][8];
#pragma unroll
        for (int i = 0; i < 8; i++)
#pragma unroll
            for (int j = 0; j < 8; j++) s[i][j] = 0.f;
#pragma unroll 8
        for (int kk = 0; kk < 64; kk++) {
            float ra[8], rb[8];
#pragma unroll
            for (int i = 0; i < 8; i++) ra[i] = Qs[kk * TSTR + ty * 8 + i];
#pragma unroll
            for (int j = 0; j < 8; j++) rb[j] = Ks[kk * TSTR + tx * 8 + j];
#pragma unroll
            for (int i = 0; i < 8; i++)
#pragma unroll
                for (int j = 0; j < 8; j++) s[i][j] += ra[i] * rb[j];
        }

        // scale + causal mask (only diagonal tile needs it)
        if (kt == qt) {
#pragma unroll
            for (int i = 0; i < 8; i++)
#pragma unroll
                for (int j = 0; j < 8; j++)
                    s[i][j] = (tx * 8 + j > ty * 8 + i) ? -9e15f : s[i][j] * scale;
        } else {
#pragma unroll
            for (int i = 0; i < 8; i++)
#pragma unroll
                for (int j = 0; j < 8; j++) s[i][j] *= scale;
        }

        // ---- per-row online softmax update (16-lane shuffle reduce) ----
#pragma unroll
        for (int i = 0; i < 8; i++) {
            float tmax = s[i][0];
#pragma unroll
            for (int j = 1; j < 8; j++) tmax = fmaxf(tmax, s[i][j]);
#pragma unroll
            for (int d = 1; d < 16; d <<= 1)
                tmax = fmaxf(tmax, __shfl_xor_sync(0xffffffffu, tmax, d));
            const float m_new = fmaxf(m_st[i], tmax);
            const float corr  = __expf(m_st[i] - m_new);
            float psum = 0.f;
#pragma unroll
            for (int j = 0; j < 8; j++) {
                float e = __expf(s[i][j] - m_new);
                s[i][j] = e;
                psum += e;
            }
#pragma unroll
            for (int d = 1; d < 16; d <<= 1)
                psum += __shfl_xor_sync(0xffffffffu, psum, d);
            l_st[i] = l_st[i] * corr + psum;
            m_st[i] = m_new;
#pragma unroll
            for (int j = 0; j < 4; j++) o[i][j] *= corr;
            if (tx == 0)
                mrun[((size_t)bh * SLEN + q0 + ty * 8 + i) * NTILE + kt] = m_new;
        }

        // ---- write unnormalized e to attn_out + stage into Ps ----
#pragma unroll
        for (int i = 0; i < 8; i++) {
            float* arow = abh + (size_t)(q0 + ty * 8 + i) * SLEN + k0 + tx * 8;
            float* prow = Ps + (ty * 8 + i) * TSTR + tx * 8;
            float4 v0, v1;
            v0.x = s[i][0]; v0.y = s[i][1]; v0.z = s[i][2]; v0.w = s[i][3];
            v1.x = s[i][4]; v1.y = s[i][5]; v1.z = s[i][6]; v1.w = s[i][7];
            *(float4*)(arow)     = v0;
            *(float4*)(arow + 4) = v1;
            *(float4*)(prow)     = v0;
            *(float4*)(prow + 4) = v1;
        }
        __syncthreads();   // Ps + Vs ready for all threads

        // ---- O += P V (8 rows x 4 cols per thread, kk over 128) ----
#pragma unroll 4
        for (int kk = 0; kk < 128; kk++) {
            float pa[8], vb[4];
#pragma unroll
            for (int i = 0; i < 8; i++) pa[i] = Ps[(ty * 8 + i) * TSTR + kk];
#pragma unroll
            for (int j = 0; j < 4; j++) vb[j] = Vs[kk * 64 + tx * 4 + j];
#pragma unroll
            for (int i = 0; i < 8; i++)
#pragma unroll
                for (int j = 0; j < 4; j++) o[i][j] += pa[i] * vb[j];
        }
        __syncthreads();   // before next tile overwrites Ks/Vs/Ps
    }

    // ---- zero strict-upper tiles (exact zeros required; d_out is poisoned) ----
    {
        const float4 z = make_float4(0.f, 0.f, 0.f, 0.f);
        for (int kt = qt + 1; kt < NTILE; kt++) {
            const int k0 = kt * 128;
#pragma unroll
            for (int i = 0; i < 8; i++) {
                float* arow = abh + (size_t)(q0 + ty * 8 + i) * SLEN + k0 + tx * 8;
                *(float4*)(arow)     = z;
                *(float4*)(arow + 4) = z;
            }
        }
    }

    // ---- finalize O and store row denominators ----
#pragma unroll
    for (int i = 0; i < 8; i++) {
        const int r = q0 + ty * 8 + i;
        const float linv = 1.f / l_st[i];
        if (tx == 0) lfin[(size_t)bh * SLEN + r] = l_st[i];
        float4 v;
        v.x = o[i][0] * linv; v.y = o[i][1] * linv;
        v.z = o[i][2] * linv; v.w = o[i][3] * linv;
        *(float4*)&vals[((size_t)b * SLEN + r) * EDIM + h * HDIM + tx * 4] = v;
    }
}

// ---------------------------------------------------------------------------
// Fixup: attn[r][tile kt] *= exp(m_run[r][kt] - m_final[r]) / l[r]
// Block = (qt, bh): 128 rows x (qt+1) k-tiles. Memory-bound.
// ---------------------------------------------------------------------------
__global__ __launch_bounds__(256)
void attn_fixup(float* __restrict__ attn_out,
                const float* __restrict__ mrun,
                const float* __restrict__ lfin) {
    __shared__ float fac[128][NTILE + 1];

    const int qt = blockIdx.x;
    const int bh = blockIdx.y;
    const int q0 = qt * 128;
    const int tid = threadIdx.x;
    const int nk = qt + 1;

    for (int idx = tid; idx < 128 * nk; idx += 256) {
        const int r  = idx / nk;
        const int kt = idx - r * nk;
        const size_t row = (size_t)bh * SLEN + q0 + r;
        const float m_fin = mrun[row * NTILE + qt];
        const float linv  = 1.f / lfin[row];
        fac[r][kt] = __expf(mrun[row * NTILE + kt] - m_fin) * linv;
    }
    __syncthreads();

    float* base = attn_out + (size_t)bh * SLEN * SLEN + (size_t)q0 * SLEN;
    const int cols4 = nk * 32;                 // float4s per row (lower region)
    const int total = 128 * cols4;
    for (int e = tid; e < total; e += 256) {
        const int r  = e / cols4;
        const int c4 = (e - r * cols4) << 2;
        const float f = fac[r][c4 >> 7];
        float4* p = (float4*)(base + (size_t)r * SLEN + c4);
        float4 v = *p;
        v.x *= f; v.y *= f; v.z *= f; v.w *= f;
        *p = v;
    }
}

// ---------------------------------------------------------------------------
// Launch
// ---------------------------------------------------------------------------
extern "C" void kernel_launch(void* const* d_in, const int* in_sizes, int n_in,
                              void* d_out, int out_size) {
    const float* x     = (const float*)d_in[0];   // [B,S,E]
    const float* w_qkv = (const float*)d_in[1];   // [E,3E]
    const float* b_qkv = (const float*)d_in[2];   // [3E]
    const float* w_o   = (const float*)d_in[3];   // [E,E]
    const float* b_o   = (const float*)d_in[4];   // [E]
    // d_in[5] = mask (causal tril) -- structure known, not read

    float* out      = (float*)d_out;
    float* o_out    = out;                                        // [B,S,E]
    float* attn_out = out + (size_t)BATCH * SLEN * EDIM;          // [B,H,S,S]

    float *qkv = nullptr, *vals = nullptr, *mrun = nullptr, *lfin = nullptr;
    cudaGetSymbolAddress((void**)&qkv,  g_qkv);
    cudaGetSymbolAddress((void**)&vals, g_vals);
    cudaGetSymbolAddress((void**)&mrun, g_mrun);
    cudaGetSymbolAddress((void**)&lfin, g_lfin);

    cudaFuncSetAttribute(attn_kernel, cudaFuncAttributeMaxDynamicSharedMemorySize,
                         ATT_SM_BYTES);

    const int M = BATCH * SLEN;  // 8192

    // 1) QKV projection: [8192,1024] x [1024,3072]
    {
        dim3 grid(QKVW / 128, M / 128);
        sgemm_bias<<<grid, 256>>>(x, w_qkv, b_qkv, qkv, M, QKVW, EDIM);
    }
    // 2) single-pass attention (unnormalized attn + exact O partials)
    {
        dim3 grid(NTILE, BATCH * NH);
        attn_kernel<<<grid, 256, ATT_SM_BYTES>>>(qkv, attn_out, mrun, lfin, vals);
    }
    // 3) normalize attention matrix
    {
        dim3 grid(NTILE, BATCH * NH);
        attn_fixup<<<grid, 256>>>(attn_out, mrun, lfin);
    }
    // 4) output projection: [8192,1024] x [1024,1024]
    {
        dim3 grid(EDIM / 128, M / 128);
        sgemm_bias<<<grid, 256>>>(vals, w_o, b_o, o_out, M, EDIM, EDIM);
    }
}

// round 14
// speedup vs baseline: 1.9006x; 1.9006x over previous
#include <cuda_runtime.h>
#include <cuda_bf16.h>
#include <math.h>
#include <stdint.h>

// Problem constants
#define BATCH 4
#define SLEN  2048
#define EDIM  1024
#define NH    16
#define HDIM  64
#define QKVW  3072            // 3*E
#define HSTRIDE 192           // 3*HD per head inside qkv row

// ---------------------------------------------------------------------------
// Scratch (device globals: allocation is forbidden)
// ---------------------------------------------------------------------------
__device__ float g_qkv [(size_t)BATCH * SLEN * QKVW];        // [B*S, 3E] fp32
__device__ float g_vals[(size_t)BATCH * SLEN * EDIM];        // [B*S, E]  fp32
__device__ __nv_bfloat16 g_Ahi[(size_t)BATCH * SLEN * EDIM]; // activation split hi
__device__ __nv_bfloat16 g_Alo[(size_t)BATCH * SLEN * EDIM]; // activation split lo
__device__ __nv_bfloat16 g_Wqhi[(size_t)QKVW * EDIM];        // w_qkv^T [3072][1024]
__device__ __nv_bfloat16 g_Wqlo[(size_t)QKVW * EDIM];
__device__ __nv_bfloat16 g_Wohi[(size_t)EDIM * EDIM];        // w_o^T [1024][1024]
__device__ __nv_bfloat16 g_Wolo[(size_t)EDIM * EDIM];

// ---------------------------------------------------------------------------
// PTX helpers (all base-target sm_80+ features; NO tcgen05 — ptxas here
// targets sm_103 base, which rejects arch-specific instructions)
// ---------------------------------------------------------------------------
__device__ __forceinline__ uint32_t smem_u32(const void* p) {
    uint32_t a;
    asm("{ .reg .u64 t; cvta.to.shared.u64 t, %1; cvt.u32.u64 %0, t; }"
        : "=r"(a) : "l"(p));
    return a;
}

#define CP16(saddr, gptr)                                                      \
    asm volatile("cp.async.cg.shared.global [%0], [%1], 16;"                   \
                 :: "r"(saddr), "l"(gptr) : "memory")
#define CP_COMMIT() asm volatile("cp.async.commit_group;" ::: "memory")
#define CP_WAIT1()  asm volatile("cp.async.wait_group 1;" ::: "memory")
#define CP_WAIT0()  asm volatile("cp.async.wait_group 0;" ::: "memory")

#define LDSM4(r, addr)                                                         \
    asm volatile("ldmatrix.sync.aligned.m8n8.x4.shared.b16 {%0,%1,%2,%3}, [%4];" \
                 : "=r"((r)[0]), "=r"((r)[1]), "=r"((r)[2]), "=r"((r)[3])      \
                 : "r"(addr))
#define LDSM2(r, addr)                                                         \
    asm volatile("ldmatrix.sync.aligned.m8n8.x2.shared.b16 {%0,%1}, [%2];"     \
                 : "=r"((r)[0]), "=r"((r)[1]) : "r"(addr))

#define MMA_BF16(d, a, b)                                                      \
    asm volatile("mma.sync.aligned.m16n8k16.row.col.f32.bf16.bf16.f32 "        \
                 "{%0,%1,%2,%3}, {%4,%5,%6,%7}, {%8,%9}, {%0,%1,%2,%3};"       \
                 : "+f"((d)[0]), "+f"((d)[1]), "+f"((d)[2]), "+f"((d)[3])      \
                 : "r"((a)[0]), "r"((a)[1]), "r"((a)[2]), "r"((a)[3]),         \
                   "r"((b)[0]), "r"((b)[1]))

// ---------------------------------------------------------------------------
// fp32 -> (hi, lo) bf16 split, elementwise
// ---------------------------------------------------------------------------
__global__ __launch_bounds__(256)
void split_convert(const float* __restrict__ src, __nv_bfloat16* __restrict__ hi,
                   __nv_bfloat16* __restrict__ lo, int n4) {
    int i = blockIdx.x * 256 + threadIdx.x;
    if (i >= n4) return;
    float4 v = ((const float4*)src)[i];
    __nv_bfloat16 h0 = __float2bfloat16_rn(v.x);
    __nv_bfloat16 h1 = __float2bfloat16_rn(v.y);
    __nv_bfloat16 h2 = __float2bfloat16_rn(v.z);
    __nv_bfloat16 h3 = __float2bfloat16_rn(v.w);
    __nv_bfloat16 l0 = __float2bfloat16_rn(v.x - __bfloat162float(h0));
    __nv_bfloat16 l1 = __float2bfloat16_rn(v.y - __bfloat162float(h1));
    __nv_bfloat16 l2 = __float2bfloat16_rn(v.z - __bfloat162float(h2));
    __nv_bfloat16 l3 = __float2bfloat16_rn(v.w - __bfloat162float(h3));
    ((__nv_bfloat162*)hi)[2 * i]     = __nv_bfloat162(h0, h1);
    ((__nv_bfloat162*)hi)[2 * i + 1] = __nv_bfloat162(h2, h3);
    ((__nv_bfloat162*)lo)[2 * i]     = __nv_bfloat162(l0, l1);
    ((__nv_bfloat162*)lo)[2 * i + 1] = __nv_bfloat162(l2, l3);
}

// ---------------------------------------------------------------------------
// w [K][N] fp32 -> wT hi/lo [N][K] bf16 (tiled transpose + split)
// ---------------------------------------------------------------------------
__global__ __launch_bounds__(256)
void transpose_split(const float* __restrict__ w, __nv_bfloat16* __restrict__ thi,
                     __nv_bfloat16* __restrict__ tlo, int K, int N) {
    __shared__ float t[32][33];
    const int tx = threadIdx.x, ty = threadIdx.y;
    const int n0 = blockIdx.x * 32, k0 = blockIdx.y * 32;
#pragma unroll
    for (int j = 0; j < 32; j += 8)
        t[ty + j][tx] = w[(size_t)(k0 + ty + j) * N + n0 + tx];
    __syncthreads();
#pragma unroll
    for (int j = 0; j < 32; j += 8) {
        float v = t[tx][ty + j];
        __nv_bfloat16 h = __float2bfloat16_rn(v);
        __nv_bfloat16 l = __float2bfloat16_rn(v - __bfloat162float(h));
        thi[(size_t)(n0 + ty + j) * K + k0 + tx] = h;
        tlo[(size_t)(n0 + ty + j) * K + k0 + tx] = l;
    }
}

// ---------------------------------------------------------------------------
// HMMA GEMM: C[M,N] = A * B^T + bias, split-bf16 3-term compensated.
// A hi/lo: [M][K] bf16 K-major; B hi/lo: [N][K] bf16 K-major.
// CTA tile 128x128, BK=32, 256 threads (8 warps, 2x4), warp tile 64x32.
// Smem rows padded to 40 bf16 (80 B): 8-row ldmatrix group is conflict-free.
// Double-buffered cp.async.
// ---------------------------------------------------------------------------
#define TILEB   10240u                   // 128 rows * 80 B
#define BUFB    (4u * TILEB)             // Ahi, Alo, Bhi, Blo
#define GEMM_SM_BYTES (2 * BUFB)         // 81920 B

__global__ __launch_bounds__(256)
void gemm_mma(const __nv_bfloat16* __restrict__ Ahi, const __nv_bfloat16* __restrict__ Alo,
              const __nv_bfloat16* __restrict__ Bhi, const __nv_bfloat16* __restrict__ Blo,
              const float* __restrict__ bias, float* __restrict__ C,
              int M, int N, int K) {
    extern __shared__ char gsm[];
    const uint32_t sbase = smem_u32(gsm);

    const int tid  = threadIdx.x;
    const int wid  = tid >> 5;
    const int lane = tid & 31;
    const int wm   = wid >> 2;          // 0..1
    const int wn   = wid & 3;           // 0..3
    const int m0   = blockIdx.y * 128;
    const int n0   = blockIdx.x * 128;

    // cp.async: 512 16B-chunks per tile / 256 threads = 2 chunks (rows r0, r0+64)
    const int r0 = tid >> 2;
    const int c0 = tid & 3;
    const size_t gAo0 = (size_t)(m0 + r0)      * K + c0 * 8;
    const size_t gAo1 = (size_t)(m0 + r0 + 64) * K + c0 * 8;
    const size_t gBo0 = (size_t)(n0 + r0)      * K + c0 * 8;
    const size_t gBo1 = (size_t)(n0 + r0 + 64) * K + c0 * 8;
    const uint32_t so0 = (uint32_t)(r0 * 80 + c0 * 16);
    const uint32_t so1 = so0 + 64u * 80u;

#define LOAD_TILES(buf, kc) do {                                               \
    const uint32_t sb_ = sbase + (buf) * BUFB;                                 \
    CP16(sb_ + so0,             Ahi + gAo0 + (kc));                            \
    CP16(sb_ + so1,             Ahi + gAo1 + (kc));                            \
    CP16(sb_ + TILEB + so0,     Alo + gAo0 + (kc));                            \
    CP16(sb_ + TILEB + so1,     Alo + gAo1 + (kc));                            \
    CP16(sb_ + 2 * TILEB + so0, Bhi + gBo0 + (kc));                            \
    CP16(sb_ + 2 * TILEB + so1, Bhi + gBo1 + (kc));                            \
    CP16(sb_ + 3 * TILEB + so0, Blo + gBo0 + (kc));                            \
    CP16(sb_ + 3 * TILEB + so1, Blo + gBo1 + (kc));                            \
    CP_COMMIT();                                                               \
} while (0)

    float acc[4][4][4];
#pragma unroll
    for (int i = 0; i < 4; i++)
#pragma unroll
        for (int j = 0; j < 4; j++)
#pragma unroll
            for (int r = 0; r < 4; r++) acc[i][j][r] = 0.f;

    // ldmatrix lane addressing
    const int arow = (lane & 7) + ((lane >> 3) & 1) * 8;  // m within 16
    const int acol = (lane >> 4) * 8;                     // k-half
    const int brow = lane & 7;                            // n within 8
    const int bcol = ((lane >> 3) & 1) * 8;               // k-half

    const int nIter = K >> 5;       // K/32
    LOAD_TILES(0, 0);

    for (int it = 0; it < nIter; it++) {
        const int buf = it & 1;
        if (it + 1 < nIter) {
            LOAD_TILES(buf ^ 1, (it + 1) * 32);
            CP_WAIT1();
        } else {
            CP_WAIT0();
        }
        __syncthreads();

        const uint32_t sb = sbase + buf * BUFB;
#pragma unroll
        for (int ks = 0; ks < 32; ks += 16) {
            uint32_t ah[4][4], al[4][4], bh[4][2], bl[4][2];
#pragma unroll
            for (int mt = 0; mt < 4; mt++) {
                const uint32_t ad = sb +
                    (uint32_t)((wm * 64 + mt * 16 + arow) * 80 + (ks + acol) * 2);
                LDSM4(ah[mt], ad);
                LDSM4(al[mt], ad + TILEB);
            }
#pragma unroll
            for (int nt = 0; nt < 4; nt++) {
                const uint32_t bd = sb + 2 * TILEB +
                    (uint32_t)((wn * 32 + nt * 8 + brow) * 80 + (ks + bcol) * 2);
                LDSM2(bh[nt], bd);
                LDSM2(bl[nt], bd + TILEB);
            }
#pragma unroll
            for (int mt = 0; mt < 4; mt++)
#pragma unroll
                for (int nt = 0; nt < 4; nt++) {
                    MMA_BF16(acc[mt][nt], ah[mt], bh[nt]);
                    MMA_BF16(acc[mt][nt], ah[mt], bl[nt]);
                    MMA_BF16(acc[mt][nt], al[mt], bh[nt]);
                }
        }
        __syncthreads();
    }

    // ---- epilogue: fragment -> gmem with bias ----
    const int erow = lane >> 2;
    const int ecol = (lane & 3) * 2;
#pragma unroll
    for (int mt = 0; mt < 4; mt++) {
        const int row = m0 + wm * 64 + mt * 16 + erow;
#pragma unroll
        for (int nt = 0; nt < 4; nt++) {
            const int col = n0 + wn * 32 + nt * 8 + ecol;
            const float b0 = bias[col], b1 = bias[col + 1];
            float2 v0, v1;
            v0.x = acc[mt][nt][0] + b0; v0.y = acc[mt][nt][1] + b1;
            v1.x = acc[mt][nt][2] + b0; v1.y = acc[mt][nt][3] + b1;
            *(float2*)&C[(size_t)row * N + col]       = v0;
            *(float2*)&C[(size_t)(row + 8) * N + col] = v1;
        }
    }
#undef LOAD_TILES
}

// ---------------------------------------------------------------------------
// Attention (known-good two-pass version, 64x64 tiles) — unchanged
// ---------------------------------------------------------------------------
#define TPAD 65
#define SM_FLOATS (3 * 64 * TPAD + 128)
#define SM_BYTES  (SM_FLOATS * 4)

__device__ __forceinline__ void load_tile64(float* dst, const float* __restrict__ qkv,
                                            int b, int s0, int h, int off, int tid) {
    const float* base = qkv + ((size_t)b * SLEN + s0) * QKVW + h * HSTRIDE + off;
#pragma unroll
    for (int i = 0; i < 4; i++) {
        int idx = tid + i * 256;
        int r   = idx >> 4;
        int c4  = (idx & 15) << 2;
        float4 v = *(const float4*)(base + (size_t)r * QKVW + c4);
        float* d = dst + r * TPAD + c4;
        d[0] = v.x; d[1] = v.y; d[2] = v.z; d[3] = v.w;
    }
}

__global__ __launch_bounds__(256)
void attn_kernel(const float* __restrict__ qkv,
                 float* __restrict__ attn_out,   // [B,H,S,S]
                 float* __restrict__ vals) {     // [B,S,E]
    extern __shared__ float smf[];
    float* Qs   = smf;
    float* Ks   = smf + 64 * TPAD;
    float* Ps   = smf + 2 * 64 * TPAD;
    float* mrow = smf + 3 * 64 * TPAD;
    float* lrow = mrow + 64;

    const int qt  = blockIdx.x;
    const int bh  = blockIdx.y;
    const int b   = bh >> 4;
    const int h   = bh & 15;
    const int tid = threadIdx.x;
    const int tx  = tid & 15;
    const int ty  = tid >> 4;
    const int q0  = qt * 64;

    load_tile64(Qs, qkv, b, q0, h, 0, tid);
    if (tid < 64) { mrow[tid] = -INFINITY; lrow[tid] = 0.f; }
    __syncthreads();

    const float scale = 0.125f;

    // Pass 1: softmax stats
    for (int kt = 0; kt <= qt; kt++) {
        load_tile64(Ks, qkv, b, kt * 64, h, HDIM, tid);
        __syncthreads();

        float s[4][4];
#pragma unroll
        for (int i = 0; i < 4; i++)
#pragma unroll
            for (int j = 0; j < 4; j++) s[i][j] = 0.f;
#pragma unroll 16
        for (int kk = 0; kk < 64; kk++) {
            float ra[4], rb[4];
#pragma unroll
            for (int i = 0; i < 4; i++) ra[i] = Qs[(ty * 4 + i) * TPAD + kk];
#pragma unroll
            for (int j = 0; j < 4; j++) rb[j] = Ks[(tx * 4 + j) * TPAD + kk];
#pragma unroll
            for (int i = 0; i < 4; i++)
#pragma unroll
                for (int j = 0; j < 4; j++) s[i][j] += ra[i] * rb[j];
        }
#pragma unroll
        for (int i = 0; i < 4; i++)
#pragma unroll
            for (int j = 0; j < 4; j++) {
                s[i][j] *= scale;
                if (kt == qt && (tx * 4 + j) > (ty * 4 + i)) s[i][j] = -9e15f;
            }
#pragma unroll
        for (int i = 0; i < 4; i++) {
            const int qr = ty * 4 + i;
            float tmax = fmaxf(fmaxf(s[i][0], s[i][1]), fmaxf(s[i][2], s[i][3]));
#pragma unroll
            for (int d = 1; d < 16; d <<= 1)
                tmax = fmaxf(tmax, __shfl_xor_sync(0xffffffffu, tmax, d));
            const float m_old = mrow[qr];
            const float m_new = fmaxf(m_old, tmax);
            float psum = 0.f;
#pragma unroll
            for (int j = 0; j < 4; j++) psum += __expf(s[i][j] - m_new);
#pragma unroll
            for (int d = 1; d < 16; d <<= 1)
                psum += __shfl_xor_sync(0xffffffffu, psum, d);
            if (tx == 0) {
                mrow[qr] = m_new;
                lrow[qr] = lrow[qr] * __expf(m_old - m_new) + psum;
            }
        }
        __syncthreads();
    }

    // Pass 2: write attn + P@V
    float mf[4], linv[4];
#pragma unroll
    for (int i = 0; i < 4; i++) {
        mf[i]   = mrow[ty * 4 + i];
        linv[i] = 1.f / lrow[ty * 4 + i];
    }
    float o[4][4];
#pragma unroll
    for (int i = 0; i < 4; i++)
#pragma unroll
        for (int j = 0; j < 4; j++) o[i][j] = 0.f;

    float* attn_base = attn_out + ((size_t)bh * SLEN + q0) * SLEN;

    for (int kt = 0; kt < SLEN / 64; kt++) {
        const int k0 = kt * 64;
        if (kt <= qt) {
            load_tile64(Ks, qkv, b, k0, h, HDIM, tid);
            __syncthreads();

            float s[4][4];
#pragma unroll
            for (int i = 0; i < 4; i++)
#pragma unroll
                for (int j = 0; j < 4; j++) s[i][j] = 0.f;
#pragma unroll 16
            for (int kk = 0; kk < 64; kk++) {
                float ra[4], rb[4];
#pragma unroll
                for (int i = 0; i < 4; i++) ra[i] = Qs[(ty * 4 + i) * TPAD + kk];
#pragma unroll
                for (int j = 0; j < 4; j++) rb[j] = Ks[(tx * 4 + j) * TPAD + kk];
#pragma unroll
                for (int i = 0; i < 4; i++)
#pragma unroll
                    for (int j = 0; j < 4; j++) s[i][j] += ra[i] * rb[j];
            }
#pragma unroll
            for (int i = 0; i < 4; i++) {
                float4 pv;
                float p[4];
#pragma unroll
                for (int j = 0; j < 4; j++) {
                    float sv = s[i][j] * scale;
                    if (kt == qt && (tx * 4 + j) > (ty * 4 + i)) sv = -9e15f;
                    p[j] = __expf(sv - mf[i]) * linv[i];
                    Ps[(ty * 4 + i) * TPAD + tx * 4 + j] = p[j];
                }
                pv.x = p[0]; pv.y = p[1]; pv.z = p[2]; pv.w = p[3];
                *(float4*)(attn_base + (size_t)(ty * 4 + i) * SLEN + k0 + tx * 4) = pv;
            }
            __syncthreads();

            load_tile64(Ks, qkv, b, k0, h, 2 * HDIM, tid); // V
            __syncthreads();

#pragma unroll 16
            for (int kk = 0; kk < 64; kk++) {
                float pa[4], vb[4];
#pragma unroll
                for (int i = 0; i < 4; i++) pa[i] = Ps[(ty * 4 + i) * TPAD + kk];
#pragma unroll
                for (int j = 0; j < 4; j++) vb[j] = Ks[kk * TPAD + tx * 4 + j];
#pragma unroll
                for (int i = 0; i < 4; i++)
#pragma unroll
                    for (int j = 0; j < 4; j++) o[i][j] += pa[i] * vb[j];
            }
            __syncthreads();
        } else {
            const float4 z = make_float4(0.f, 0.f, 0.f, 0.f);
#pragma unroll
            for (int i = 0; i < 4; i++)
                *(float4*)(attn_base + (size_t)(ty * 4 + i) * SLEN + k0 + tx * 4) = z;
        }
    }

#pragma unroll
    for (int i = 0; i < 4; i++) {
        const int r = q0 + ty * 4 + i;
        float4 v;
        v.x = o[i][0]; v.y = o[i][1]; v.z = o[i][2]; v.w = o[i][3];
        *(float4*)&vals[((size_t)b * SLEN + r) * EDIM + h * HDIM + tx * 4] = v;
    }
}

// ---------------------------------------------------------------------------
// Launch
// ---------------------------------------------------------------------------
extern "C" void kernel_launch(void* const* d_in, const int* in_sizes, int n_in,
                              void* d_out, int out_size) {
    const float* x     = (const float*)d_in[0];   // [B,S,E]
    const float* w_qkv = (const float*)d_in[1];   // [E,3E]
    const float* b_qkv = (const float*)d_in[2];   // [3E]
    const float* w_o   = (const float*)d_in[3];   // [E,E]
    const float* b_o   = (const float*)d_in[4];   // [E]

    float* out      = (float*)d_out;
    float* o_out    = out;                                        // [B,S,E]
    float* attn_out = out + (size_t)BATCH * SLEN * EDIM;          // [B,H,S,S]

    float *qkv = nullptr, *vals = nullptr;
    __nv_bfloat16 *Ahi = nullptr, *Alo = nullptr;
    __nv_bfloat16 *Wqhi = nullptr, *Wqlo = nullptr, *Wohi = nullptr, *Wolo = nullptr;
    cudaGetSymbolAddress((void**)&qkv,  g_qkv);
    cudaGetSymbolAddress((void**)&vals, g_vals);
    cudaGetSymbolAddress((void**)&Ahi,  g_Ahi);
    cudaGetSymbolAddress((void**)&Alo,  g_Alo);
    cudaGetSymbolAddress((void**)&Wqhi, g_Wqhi);
    cudaGetSymbolAddress((void**)&Wqlo, g_Wqlo);
    cudaGetSymbolAddress((void**)&Wohi, g_Wohi);
    cudaGetSymbolAddress((void**)&Wolo, g_Wolo);

    cudaFuncSetAttribute(attn_kernel, cudaFuncAttributeMaxDynamicSharedMemorySize, SM_BYTES);
    cudaFuncSetAttribute(gemm_mma, cudaFuncAttributeMaxDynamicSharedMemorySize, GEMM_SM_BYTES);

    const int M = BATCH * SLEN;            // 8192
    const int nElem = M * EDIM;            // 8388608

    // 0) operand preparation
    split_convert<<<nElem / 1024, 256>>>(x, Ahi, Alo, nElem / 4);
    {
        dim3 blk(32, 8);
        transpose_split<<<dim3(QKVW / 32, EDIM / 32), blk>>>(w_qkv, Wqhi, Wqlo, EDIM, QKVW);
        transpose_split<<<dim3(EDIM / 32, EDIM / 32), blk>>>(w_o,   Wohi, Wolo, EDIM, EDIM);
    }
    // 1) QKV projection (HMMA): [8192,1024] x [1024,3072]
    {
        dim3 grid(QKVW / 128, M / 128);
        gemm_mma<<<grid, 256, GEMM_SM_BYTES>>>(Ahi, Alo, Wqhi, Wqlo, b_qkv, qkv,
                                               M, QKVW, EDIM);
    }
    // 2) attention
    {
        dim3 grid(SLEN / 64, BATCH * NH);
        attn_kernel<<<grid, 256, SM_BYTES>>>(qkv, attn_out, vals);
    }
    // 3) split vals, then O projection (HMMA)
    split_convert<<<nElem / 1024, 256>>>(vals, Ahi, Alo, nElem / 4);
    {
        dim3 grid(EDIM / 128, M / 128);
        gemm_mma<<<grid, 256, GEMM_SM_BYTES>>>(Ahi, Alo, Wohi, Wolo, b_o, o_out,
                                               M, EDIM, EDIM);
    }
}